// round 11
// baseline (speedup 1.0000x reference)
#include <cuda_runtime.h>
#include <cstdint>

#define CIN 4
#define COUT 8
#define HH 512
#define WW 512

// Prepacked weights: [half][c][ky][kx][co4][i] -> float2 (j=0, j=1 weight rows)
__device__ float2 g_wpk[576];
__constant__ float2 c_wpk[576];

__global__ void prepack_kernel(const float* __restrict__ w) {
    int idx = threadIdx.x;
    if (idx >= 576) return;
    int i = idx & 1;
    int t = idx >> 1;
    int co4 = t & 3; t >>= 2;
    int kx = t % 3; t /= 3;
    int ky = t % 3; t /= 3;
    int c  = t & 3; t >>= 2;
    int half = t;                       // 0 or 1
    int g  = half * 2 + (co4 >> 1);     // group = co>>1
    int ct = c * 9 + ky * 3 + kx;
    int r0 = (co4 & 1) * 4 + 2 * i;     // weight row for j=0; +1 for j=1
    float2 val;
    val.x = w[(g * 8 + r0) * 36 + ct];
    val.y = w[(g * 8 + r0 + 1) * 36 + ct];
    g_wpk[idx] = val;
}

__device__ __forceinline__ unsigned long long pack2(float a, float b) {
    unsigned long long r;
    asm("mov.b64 %0, {%1, %2};" : "=l"(r) : "f"(a), "f"(b));
    return r;
}
__device__ __forceinline__ void unpack2(unsigned long long p, float& a, float& b) {
    asm("mov.b64 {%0, %1}, %2;" : "=f"(a), "=f"(b) : "l"(p));
}
__device__ __forceinline__ void ffma2(unsigned long long& d, unsigned long long a, unsigned long long b) {
    asm("fma.rn.f32x2 %0, %1, %2, %0;" : "+l"(d) : "l"(a), "l"(b));
}

__global__ __launch_bounds__(128, 6)
void conv_kernel(const float* __restrict__ x, float* __restrict__ out) {
    int tid = threadIdx.x;

    int half = blockIdx.x & 1;                // channel half (co>>2)
    int h    = (blockIdx.x >> 1) & 255;       // tile row 0..255
    int b    = blockIdx.x >> 9;               // batch 0..7

    int x0 = tid << 2;                        // 4 output/input columns per thread

    const float* xb = x + (size_t)b * (CIN * HH * WW);
    float*       ob = out + (size_t)b * (COUT * HH * WW);

    // acc[t][co4][i] = f32x2 (out col x0+2t+0, x0+2t+1) at output row 2h+i
    unsigned long long acc[2][4][2];
    #pragma unroll
    for (int t = 0; t < 2; t++)
        #pragma unroll
        for (int q = 0; q < 4; q++) {
            acc[t][q][0] = 0ULL;
            acc[t][q][1] = 0ULL;
        }

    int ybase = 2 * h + half - 1;             // input rows ybase+ky (ci = half)
    bool ok0 = (ybase >= 0);                  // only false at h=0, half=0
    bool ok2 = (ybase + 2 < HH);              // only false at h=255, half=1
    bool pl  = (x0 > 0);
    bool pr  = (x0 < WW - 4);

    // Weight base in constant memory for this half (uniform across warp).
    const float2* cw = c_wpk + half * 288;

    // Fully unrolled mainloop over (c, ky): ptxas schedules load batching / MLP.
    #pragma unroll
    for (int c = 0; c < CIN; c++) {
        const float* xc = xb + (size_t)c * (HH * WW);
        #pragma unroll
        for (int ky = 0; ky < 3; ky++) {
            bool ok = (ky == 0) ? ok0 : ((ky == 2) ? ok2 : true);
            const float* xr = xc + (size_t)(ybase + ky) * WW + x0;
            float4 A = make_float4(0.f, 0.f, 0.f, 0.f);
            float vl = 0.f, vr = 0.f;
            if (ok) {
                A = *(const float4*)xr;
                if (pl) vl = xr[-1];
                if (pr) vr = xr[4];
            }

            // vv[m] = (v,v) packed; v[m] = input at column x0-1+m  (m = 0..5)
            unsigned long long vv[6];
            vv[0] = pack2(vl, vl);
            vv[1] = pack2(A.x, A.x);  vv[2] = pack2(A.y, A.y);
            vv[3] = pack2(A.z, A.z);  vv[4] = pack2(A.w, A.w);
            vv[5] = pack2(vr, vr);

            const ulonglong2* wk = (const ulonglong2*)(cw + (c * 3 + ky) * 24);
            #pragma unroll
            for (int kx = 0; kx < 3; kx++) {
                // 8 weight f32x2 for this tap: [co4][i] — warp-uniform constant-port loads
                ulonglong2 q0 = wk[kx * 4 + 0];
                ulonglong2 q1 = wk[kx * 4 + 1];
                ulonglong2 q2 = wk[kx * 4 + 2];
                ulonglong2 q3 = wk[kx * 4 + 3];
                #pragma unroll
                for (int t = 0; t < 2; t++) {
                    int m = 2 * t + kx;              // cj=0 channels
                    ffma2(acc[t][0][0], vv[m],     q0.x);
                    ffma2(acc[t][0][1], vv[m],     q0.y);
                    ffma2(acc[t][1][0], vv[m],     q1.x);
                    ffma2(acc[t][1][1], vv[m],     q1.y);
                    ffma2(acc[t][2][0], vv[m + 1], q2.x);  // cj=1 channels
                    ffma2(acc[t][2][1], vv[m + 1], q2.y);
                    ffma2(acc[t][3][0], vv[m + 1], q3.x);
                    ffma2(acc[t][3][1], vv[m + 1], q3.y);
                }
            }
        }
    }

    // Store: per (co, i): 4 contiguous columns -> one coalesced float4
    #pragma unroll
    for (int q = 0; q < 4; q++) {
        int co = half * 4 + q;
        #pragma unroll
        for (int i = 0; i < 2; i++) {
            int Y = 2 * h + i;
            float* op = ob + ((size_t)co * HH + Y) * WW + x0;
            float a0, a1, a2, a3;
            unpack2(acc[0][q][i], a0, a1);
            unpack2(acc[1][q][i], a2, a3);
            *(float4*)op = make_float4(a0, a1, a2, a3);
        }
    }
}

extern "C" void kernel_launch(void* const* d_in, const int* in_sizes, int n_in,
                              void* d_out, int out_size) {
    const float* x = (const float*)d_in[0];
    const float* w = (const float*)d_in[1];
    float* out = (float*)d_out;
    prepack_kernel<<<1, 576>>>(w);
    // Copy prepacked weights into the constant bank (D2D, graph-capturable).
    void* src = nullptr;
    cudaGetSymbolAddress(&src, g_wpk);
    cudaMemcpyToSymbolAsync(c_wpk, src, 576 * sizeof(float2), 0,
                            cudaMemcpyDeviceToDevice, 0);
    conv_kernel<<<4096, 128>>>(x, out);
}

// round 12
// speedup vs baseline: 1.3008x; 1.3008x over previous
#include <cuda_runtime.h>
#include <cstdint>

#define CIN 4
#define COUT 8
#define HH 512
#define WW 512

// Prepacked weights: [half][c][ky][kx][co4][i] -> float2 (j=0, j=1 weight rows)
__device__ float2 g_wpk[576];

__global__ void prepack_kernel(const float* __restrict__ w) {
    int idx = threadIdx.x;
    if (idx >= 576) return;
    int i = idx & 1;
    int t = idx >> 1;
    int co4 = t & 3; t >>= 2;
    int kx = t % 3; t /= 3;
    int ky = t % 3; t /= 3;
    int c  = t & 3; t >>= 2;
    int half = t;                       // 0 or 1
    int g  = half * 2 + (co4 >> 1);     // group = co>>1
    int ct = c * 9 + ky * 3 + kx;
    int r0 = (co4 & 1) * 4 + 2 * i;     // weight row for j=0; +1 for j=1
    float2 val;
    val.x = w[(g * 8 + r0) * 36 + ct];
    val.y = w[(g * 8 + r0 + 1) * 36 + ct];
    g_wpk[idx] = val;
}

__device__ __forceinline__ unsigned long long pack2(float a, float b) {
    unsigned long long r;
    asm("mov.b64 %0, {%1, %2};" : "=l"(r) : "f"(a), "f"(b));
    return r;
}
__device__ __forceinline__ void unpack2(unsigned long long p, float& a, float& b) {
    asm("mov.b64 {%0, %1}, %2;" : "=f"(a), "=f"(b) : "l"(p));
}
__device__ __forceinline__ void ffma2(unsigned long long& d, unsigned long long a, unsigned long long b) {
    asm("fma.rn.f32x2 %0, %1, %2, %0;" : "+l"(d) : "l"(a), "l"(b));
}

__global__ __launch_bounds__(128, 6)
void conv_kernel(const float* __restrict__ x, float* __restrict__ out) {
    __shared__ __align__(16) float2 ws[288];
    int tid = threadIdx.x;
    int lane = tid & 31;

    int half = blockIdx.x & 1;                // channel half (co>>2)
    int h    = (blockIdx.x >> 1) & 255;       // tile row 0..255
    int b    = blockIdx.x >> 9;               // batch 0..7

    // Load this half's weights (288 float2 = 2.25 KB)
    {
        const float2* src = g_wpk + half * 288;
        for (int k = tid; k < 288; k += 128) ws[k] = src[k];
    }
    __syncthreads();

    int x0 = tid << 2;                        // 4 output/input columns per thread

    const float* xb = x + (size_t)b * (CIN * HH * WW);
    float*       ob = out + (size_t)b * (COUT * HH * WW);

    // acc[t][co4][i] = f32x2 (out col x0+2t+0, x0+2t+1) at output row 2h+i
    unsigned long long acc[2][4][2];
    #pragma unroll
    for (int t = 0; t < 2; t++)
        #pragma unroll
        for (int q = 0; q < 4; q++) {
            acc[t][q][0] = 0ULL;
            acc[t][q][1] = 0ULL;
        }

    int ybase = 2 * h + half - 1;             // input rows ybase+ky (ci = half)
    bool ok0 = (ybase >= 0);                  // only false at h=0, half=0
    bool ok2 = (ybase + 2 < HH);              // only false at h=255, half=1
    // Halo ownership: block spans the full 512-col row, so halos come from
    // neighbor lanes via shfl; only warp-boundary lanes touch gmem.
    bool need_l = (lane == 0)  && (x0 > 0);        // threads 32/64/96
    bool need_r = (lane == 31) && (x0 < WW - 4);   // threads 31/63/95

    // Fully unrolled mainloop over (c, ky): ptxas schedules load batching / MLP.
    #pragma unroll
    for (int c = 0; c < CIN; c++) {
        const float* xc = xb + (size_t)c * (HH * WW);
        #pragma unroll
        for (int ky = 0; ky < 3; ky++) {
            bool ok = (ky == 0) ? ok0 : ((ky == 2) ? ok2 : true);
            const float* xr = xc + (size_t)(ybase + ky) * WW + x0;
            float4 A = make_float4(0.f, 0.f, 0.f, 0.f);
            float el = 0.f, er = 0.f;
            if (ok) {
                A = *(const float4*)xr;
                if (need_l) el = xr[-1];      // predicated, 1 lane per warp
                if (need_r) er = xr[4];       // predicated, 1 lane per warp
            }
            // Halo exchange: vl = neighbor's A.w, vr = neighbor's A.x
            float vl = __shfl_up_sync(0xffffffffu, A.w, 1);
            float vr = __shfl_down_sync(0xffffffffu, A.x, 1);
            if (lane == 0)  vl = el;          // warp boundary (or image edge -> 0)
            if (lane == 31) vr = er;

            // vv[m] = (v,v) packed; v[m] = input at column x0-1+m  (m = 0..5)
            unsigned long long vv[6];
            vv[0] = pack2(vl, vl);
            vv[1] = pack2(A.x, A.x);  vv[2] = pack2(A.y, A.y);
            vv[3] = pack2(A.z, A.z);  vv[4] = pack2(A.w, A.w);
            vv[5] = pack2(vr, vr);

            const ulonglong2* wk = (const ulonglong2*)(ws + (c * 3 + ky) * 24);
            #pragma unroll
            for (int kx = 0; kx < 3; kx++) {
                // 8 weight f32x2 for this tap: [co4][i], warp-uniform broadcast LDS.128
                ulonglong2 q0 = wk[kx * 4 + 0];
                ulonglong2 q1 = wk[kx * 4 + 1];
                ulonglong2 q2 = wk[kx * 4 + 2];
                ulonglong2 q3 = wk[kx * 4 + 3];
                #pragma unroll
                for (int t = 0; t < 2; t++) {
                    int m = 2 * t + kx;              // cj=0 channels
                    ffma2(acc[t][0][0], vv[m],     q0.x);
                    ffma2(acc[t][0][1], vv[m],     q0.y);
                    ffma2(acc[t][1][0], vv[m],     q1.x);
                    ffma2(acc[t][1][1], vv[m],     q1.y);
                    ffma2(acc[t][2][0], vv[m + 1], q2.x);  // cj=1 channels
                    ffma2(acc[t][2][1], vv[m + 1], q2.y);
                    ffma2(acc[t][3][0], vv[m + 1], q3.x);
                    ffma2(acc[t][3][1], vv[m + 1], q3.y);
                }
            }
        }
    }

    // Store: per (co, i): 4 contiguous columns -> one coalesced float4
    #pragma unroll
    for (int q = 0; q < 4; q++) {
        int co = half * 4 + q;
        #pragma unroll
        for (int i = 0; i < 2; i++) {
            int Y = 2 * h + i;
            float* op = ob + ((size_t)co * HH + Y) * WW + x0;
            float a0, a1, a2, a3;
            unpack2(acc[0][q][i], a0, a1);
            unpack2(acc[1][q][i], a2, a3);
            *(float4*)op = make_float4(a0, a1, a2, a3);
        }
    }
}

extern "C" void kernel_launch(void* const* d_in, const int* in_sizes, int n_in,
                              void* d_out, int out_size) {
    const float* x = (const float*)d_in[0];
    const float* w = (const float*)d_in[1];
    float* out = (float*)d_out;
    prepack_kernel<<<1, 576>>>(w);
    conv_kernel<<<4096, 128>>>(x, out);
}

// round 14
// speedup vs baseline: 1.3889x; 1.0677x over previous
#include <cuda_runtime.h>
#include <cstdint>

#define CIN 4
#define COUT 8
#define HH 512
#define WW 512

// Prepacked weights: [half][c][ky][kx][co4][i] -> float2 (j=0, j=1 weight rows)
__device__ float2 g_wpk[576];

__global__ void prepack_kernel(const float* __restrict__ w) {
    int idx = threadIdx.x;
    if (idx >= 576) return;
    int i = idx & 1;
    int t = idx >> 1;
    int co4 = t & 3; t >>= 2;
    int kx = t % 3; t /= 3;
    int ky = t % 3; t /= 3;
    int c  = t & 3; t >>= 2;
    int half = t;                       // 0 or 1
    int g  = half * 2 + (co4 >> 1);     // group = co>>1
    int ct = c * 9 + ky * 3 + kx;
    int r0 = (co4 & 1) * 4 + 2 * i;     // weight row for j=0; +1 for j=1
    float2 val;
    val.x = w[(g * 8 + r0) * 36 + ct];
    val.y = w[(g * 8 + r0 + 1) * 36 + ct];
    g_wpk[idx] = val;
}

__device__ __forceinline__ unsigned long long pack2(float a, float b) {
    unsigned long long r;
    asm("mov.b64 %0, {%1, %2};" : "=l"(r) : "f"(a), "f"(b));
    return r;
}
__device__ __forceinline__ void unpack2(unsigned long long p, float& a, float& b) {
    asm("mov.b64 {%0, %1}, %2;" : "=f"(a), "=f"(b) : "l"(p));
}
__device__ __forceinline__ void ffma2(unsigned long long& d, unsigned long long a, unsigned long long b) {
    asm("fma.rn.f32x2 %0, %1, %2, %0;" : "+l"(d) : "l"(a), "l"(b));
}

__global__ __launch_bounds__(128, 4)
void conv_kernel(const float* __restrict__ x, float* __restrict__ out) {
    __shared__ __align__(16) float2 ws[288];
    int tid = threadIdx.x;
    int lane = tid & 31;

    int half  = blockIdx.x & 1;               // channel half (co>>2)
    int hpair = (blockIdx.x >> 1) & 127;      // tile-row pair 0..127
    int b     = blockIdx.x >> 8;              // batch 0..7

    // Load this half's weights (288 float2 = 2.25 KB)
    {
        const float2* src = g_wpk + half * 288;
        for (int k = tid; k < 288; k += 128) ws[k] = src[k];
    }
    __syncthreads();

    int tx   = tid & 63;                      // 64 threads span one tile-row
    int hsub = tid >> 6;                      // 2 tile-rows per block
    int h    = hpair * 2 + hsub;              // tile row 0..255
    int x0   = tx << 3;                       // 8 output/input columns per thread

    const float* xb = x + (size_t)b * (CIN * HH * WW);
    float*       ob = out + (size_t)b * (COUT * HH * WW);

    // acc[t][co4][i] = f32x2 (out col x0+2t+0, x0+2t+1) at output row 2h+i
    unsigned long long acc[4][4][2];
    #pragma unroll
    for (int t = 0; t < 4; t++)
        #pragma unroll
        for (int q = 0; q < 4; q++) {
            acc[t][q][0] = 0ULL;
            acc[t][q][1] = 0ULL;
        }

    int ybase = 2 * h + half - 1;             // input rows ybase+ky (ci = half)
    bool ok0 = (ybase >= 0);                  // only false at h=0, half=0
    bool ok2 = (ybase + 2 < HH);              // only false at h=255, half=1
    // Halo ownership: row spans 2 warps; halos come from neighbor lanes via
    // shfl, only warp-boundary lanes touch gmem (or are image edge -> 0).
    bool need_l = (lane == 0)  && (x0 > 0);
    bool need_r = (lane == 31) && (x0 < WW - 8);

    // Fully unrolled mainloop over (c, ky): ptxas schedules load batching / MLP.
    #pragma unroll
    for (int c = 0; c < CIN; c++) {
        const float* xc = xb + (size_t)c * (HH * WW);
        #pragma unroll
        for (int ky = 0; ky < 3; ky++) {
            bool ok = (ky == 0) ? ok0 : ((ky == 2) ? ok2 : true);
            const float* xr = xc + (size_t)(ybase + ky) * WW + x0;
            float4 A = make_float4(0.f, 0.f, 0.f, 0.f);
            float4 Bv = make_float4(0.f, 0.f, 0.f, 0.f);
            float el = 0.f, er = 0.f;
            if (ok) {
                A  = *(const float4*)xr;
                Bv = *(const float4*)(xr + 4);
                if (need_l) el = xr[-1];      // predicated, 1 lane per warp
                if (need_r) er = xr[8];       // predicated, 1 lane per warp
            }
            // Halo exchange: vl = prev lane's Bv.w, vr = next lane's A.x
            float vl = __shfl_up_sync(0xffffffffu, Bv.w, 1);
            float vr = __shfl_down_sync(0xffffffffu, A.x, 1);
            if (lane == 0)  vl = el;
            if (lane == 31) vr = er;

            // vv[m] = (v,v) packed; v[m] = input at column x0-1+m  (m = 0..9)
            unsigned long long vv[10];
            vv[0] = pack2(vl, vl);
            vv[1] = pack2(A.x, A.x);   vv[2] = pack2(A.y, A.y);
            vv[3] = pack2(A.z, A.z);   vv[4] = pack2(A.w, A.w);
            vv[5] = pack2(Bv.x, Bv.x); vv[6] = pack2(Bv.y, Bv.y);
            vv[7] = pack2(Bv.z, Bv.z); vv[8] = pack2(Bv.w, Bv.w);
            vv[9] = pack2(vr, vr);

            const ulonglong2* wk = (const ulonglong2*)(ws + (c * 3 + ky) * 24);
            #pragma unroll
            for (int kx = 0; kx < 3; kx++) {
                // 8 weight f32x2 for this tap: [co4][i], warp-uniform broadcast LDS.128
                ulonglong2 q0 = wk[kx * 4 + 0];
                ulonglong2 q1 = wk[kx * 4 + 1];
                ulonglong2 q2 = wk[kx * 4 + 2];
                ulonglong2 q3 = wk[kx * 4 + 3];
                #pragma unroll
                for (int t = 0; t < 4; t++) {
                    int m = 2 * t + kx;              // cj=0 channels
                    ffma2(acc[t][0][0], vv[m],     q0.x);
                    ffma2(acc[t][0][1], vv[m],     q0.y);
                    ffma2(acc[t][1][0], vv[m],     q1.x);
                    ffma2(acc[t][1][1], vv[m],     q1.y);
                    ffma2(acc[t][2][0], vv[m + 1], q2.x);  // cj=1 channels
                    ffma2(acc[t][2][1], vv[m + 1], q2.y);
                    ffma2(acc[t][3][0], vv[m + 1], q3.x);
                    ffma2(acc[t][3][1], vv[m + 1], q3.y);
                }
            }
        }
    }

    // Store: per (co, i): 8 contiguous columns -> two coalesced float4s
    #pragma unroll
    for (int q = 0; q < 4; q++) {
        int co = half * 4 + q;
        #pragma unroll
        for (int i = 0; i < 2; i++) {
            int Y = 2 * h + i;
            float* op = ob + ((size_t)co * HH + Y) * WW + x0;
            float a0, a1, a2, a3, a4, a5, a6, a7;
            unpack2(acc[0][q][i], a0, a1);
            unpack2(acc[1][q][i], a2, a3);
            unpack2(acc[2][q][i], a4, a5);
            unpack2(acc[3][q][i], a6, a7);
            *(float4*)op       = make_float4(a0, a1, a2, a3);
            *(float4*)(op + 4) = make_float4(a4, a5, a6, a7);
        }
    }
}

extern "C" void kernel_launch(void* const* d_in, const int* in_sizes, int n_in,
                              void* d_out, int out_size) {
    const float* x = (const float*)d_in[0];
    const float* w = (const float*)d_in[1];
    float* out = (float*)d_out;
    prepack_kernel<<<1, 576>>>(w);
    conv_kernel<<<2048, 128>>>(x, out);
}